// round 16
// baseline (speedup 1.0000x reference)
#include <cuda_runtime.h>
#include <math.h>

#define N_NODES 100000
#define N_EDGES 1000000
#define DM 64            // model dim (= H*D)
#define FULLM 0xffffffffu

#define BM 128
#define BN 64
#define BK 32
#define GEMM_BLOCKS ((N_NODES + BM - 1) / BM)          // 782
#define NPW 8            // nodes per warp in the edge kernel

// ---------------- scratch (device globals: allocation-free) ----------------
__device__ float g_qk[(size_t)N_NODES * DM];
__device__ float g_v[(size_t)N_NODES * DM];
__device__ int   g_off[N_NODES + 1];
__device__ float g_attn_fb[(size_t)N_EDGES * 4];
__device__ float g_out_fb[(size_t)N_NODES * DM];

// ---------------- f32x2 packed-FMA helpers (sm_100+) ----------------
__device__ __forceinline__ unsigned long long pack2(float lo, float hi) {
    unsigned long long r;
    asm("mov.b64 %0, {%1,%2};" : "=l"(r) : "f"(lo), "f"(hi));
    return r;
}
__device__ __forceinline__ void unpack2(unsigned long long p, float& lo, float& hi) {
    asm("mov.b64 {%0,%1}, %2;" : "=f"(lo), "=f"(hi) : "l"(p));
}
__device__ __forceinline__ void ffma2(unsigned long long& c, unsigned long long a, unsigned long long b) {
    asm("fma.rn.f32x2 %0, %1, %2, %0;" : "+l"(c) : "l"(a), "l"(b));
}

// ---------------- fused projection GEMM: qk = A@W_qk + b_qk ; v = A@W_v + b_v ----------------
// (champion version, byte-identical)
__global__ __launch_bounds__(256) void gemm_qkv_kernel(
    const float* __restrict__ A,
    const float* __restrict__ W1, const float* __restrict__ b1,
    const float* __restrict__ W2, const float* __restrict__ b2,
    float* __restrict__ C1, float* __restrict__ C2, int M)
{
    __shared__ float As[BK][BM + 4];
    __shared__ float W1s[BK][BN + 4];
    __shared__ float W2s[BK][BN + 4];

    const int tid = threadIdx.x;
    const int tx = tid & 15;
    const int ty = tid >> 4;
    const int bm = blockIdx.x * BM;

    unsigned long long acc1[4][4], acc2[4][4];
#pragma unroll
    for (int i = 0; i < 4; i++)
#pragma unroll
        for (int j = 0; j < 4; j++) { acc1[i][j] = pack2(0.f, 0.f); acc2[i][j] = pack2(0.f, 0.f); }

    for (int kk = 0; kk < DM; kk += BK) {
#pragma unroll
        for (int i = 0; i < 4; i++) {
            int idx = tid + i * 256;
            int r = idx >> 3;
            int c4 = idx & 7;
            float4 v = make_float4(0.f, 0.f, 0.f, 0.f);
            if (bm + r < M)
                v = reinterpret_cast<const float4*>(A + (size_t)(bm + r) * DM + kk)[c4];
            As[c4 * 4 + 0][r] = v.x;
            As[c4 * 4 + 1][r] = v.y;
            As[c4 * 4 + 2][r] = v.z;
            As[c4 * 4 + 3][r] = v.w;
        }
#pragma unroll
        for (int i = 0; i < 2; i++) {
            int idx = tid + i * 256;
            int kr = idx >> 4;
            int c4 = idx & 15;
            float4 v1 = reinterpret_cast<const float4*>(W1 + (size_t)(kk + kr) * DM)[c4];
            float4 v2 = reinterpret_cast<const float4*>(W2 + (size_t)(kk + kr) * DM)[c4];
            *reinterpret_cast<float4*>(&W1s[kr][c4 * 4]) = v1;
            *reinterpret_cast<float4*>(&W2s[kr][c4 * 4]) = v2;
        }
        __syncthreads();

#pragma unroll
        for (int k = 0; k < BK; k++) {
            unsigned long long ap[4];
#pragma unroll
            for (int i = 0; i < 4; i++) {
                float2 a = *reinterpret_cast<const float2*>(&As[k][ty * 8 + 2 * i]);
                ap[i] = pack2(a.x, a.y);
            }
            float4 w1 = *reinterpret_cast<const float4*>(&W1s[k][tx * 4]);
            unsigned long long wd1[4];
            wd1[0] = pack2(w1.x, w1.x); wd1[1] = pack2(w1.y, w1.y);
            wd1[2] = pack2(w1.z, w1.z); wd1[3] = pack2(w1.w, w1.w);
#pragma unroll
            for (int i = 0; i < 4; i++)
#pragma unroll
                for (int j = 0; j < 4; j++) ffma2(acc1[i][j], ap[i], wd1[j]);
            float4 w2 = *reinterpret_cast<const float4*>(&W2s[k][tx * 4]);
            unsigned long long wd2[4];
            wd2[0] = pack2(w2.x, w2.x); wd2[1] = pack2(w2.y, w2.y);
            wd2[2] = pack2(w2.z, w2.z); wd2[3] = pack2(w2.w, w2.w);
#pragma unroll
            for (int i = 0; i < 4; i++)
#pragma unroll
                for (int j = 0; j < 4; j++) ffma2(acc2[i][j], ap[i], wd2[j]);
        }
        __syncthreads();
    }

    float4 bv1 = *reinterpret_cast<const float4*>(b1 + tx * 4);
    float4 bv2 = *reinterpret_cast<const float4*>(b2 + tx * 4);
#pragma unroll
    for (int i = 0; i < 4; i++) {
        int r0 = bm + ty * 8 + 2 * i;
        float lo[4], hi[4];
#pragma unroll
        for (int j = 0; j < 4; j++) unpack2(acc1[i][j], lo[j], hi[j]);
        if (r0 < M)
            *reinterpret_cast<float4*>(C1 + (size_t)r0 * DM + tx * 4) =
                make_float4(lo[0] + bv1.x, lo[1] + bv1.y, lo[2] + bv1.z, lo[3] + bv1.w);
        if (r0 + 1 < M)
            *reinterpret_cast<float4*>(C1 + (size_t)(r0 + 1) * DM + tx * 4) =
                make_float4(hi[0] + bv1.x, hi[1] + bv1.y, hi[2] + bv1.z, hi[3] + bv1.w);
#pragma unroll
        for (int j = 0; j < 4; j++) unpack2(acc2[i][j], lo[j], hi[j]);
        if (r0 < M)
            *reinterpret_cast<float4*>(C2 + (size_t)r0 * DM + tx * 4) =
                make_float4(lo[0] + bv2.x, lo[1] + bv2.y, lo[2] + bv2.z, lo[3] + bv2.w);
        if (r0 + 1 < M)
            *reinterpret_cast<float4*>(C2 + (size_t)(r0 + 1) * DM + tx * 4) =
                make_float4(hi[0] + bv2.x, hi[1] + bv2.y, hi[2] + bv2.z, hi[3] + bv2.w);
    }
}

// ---------------- segment offsets: binary search over sorted receivers ----------------
__global__ void offsets_kernel(const int* __restrict__ recv) {
    int n = blockIdx.x * blockDim.x + threadIdx.x;
    if (n > N_NODES) return;
    int lo = 0, hi = N_EDGES;
    while (lo < hi) {
        int mid = (lo + hi) >> 1;
        if (recv[mid] < n) lo = mid + 1; else hi = mid;
    }
    g_off[n] = lo;
}

// ---------------- fully fused edge + out-projection kernel ----------------
// Champion per-node body (4-edge main loop, scalar FFMA, NPW=8 nodes/warp),
// plus fused out-projection: the reduced ctx row (live in registers) is
// staged to a warp-private smem buffer and multiplied by W_out (block-staged
// in smem) in the stall shadow; each lane computes output cols 2*lane,
// 2*lane+1 and stores a coalesced float2 directly to the output buffer.
// Removes the separate out-GEMM kernel and all g_ctx traffic.
__global__ __launch_bounds__(256) void fused_edge_kernel(
    const int* __restrict__ senders, float* attn,
    const float* __restrict__ W_out, const float* __restrict__ b_out,
    float* __restrict__ out)
{
    __shared__ float wo_s[DM * DM];        // W_out[k][c] row-major, 16KB
    __shared__ float bo_s[DM];
    __shared__ float ctx_s[8][DM];         // per-warp ctx staging

    const int tid  = threadIdx.x;
    const int warp = tid >> 5;
    const int lane = tid & 31;
    const int gwarp = blockIdx.x * 8 + warp;

    // ---- stage W_out + bias once per block ----
#pragma unroll
    for (int i = 0; i < 4; i++) {
        int idx = tid + i * 256;           // 0..1023 float4 slots
        reinterpret_cast<float4*>(wo_s)[idx] =
            reinterpret_cast<const float4*>(W_out)[idx];
    }
    if (tid < DM) bo_s[tid] = b_out[tid];
    __syncthreads();

    const int t  = lane & 15;
    const int eo = lane >> 4;
    const int hq = t >> 2;
    const int h4 = lane & 3;
    const int eo8 = lane >> 2;

    for (int ni = 0; ni < NPW; ni++) {
        const int n = gwarp * NPW + ni;
        if (n >= N_NODES) return;

        const int beg = g_off[n];
        const int end = g_off[n + 1];

        float x0 = 0.f, x1 = 0.f, x2 = 0.f, x3 = 0.f;

        if (beg < end) {
            const float4 q = *reinterpret_cast<const float4*>(g_qk + (size_t)n * DM + 4 * t);
            float z = 0.f;

            int base = beg;
            // main loop: 4 edges per iteration, no guards
            for (; base + 3 < end; base += 4) {
                int ea = base + eo;
                int eb = base + 2 + eo;
                int sa = senders[ea];
                int sb = senders[eb];
                const float4 ka = *reinterpret_cast<const float4*>(g_qk + (size_t)sa * DM + 4 * t);
                const float4 va = *reinterpret_cast<const float4*>(g_v  + (size_t)sa * DM + 4 * t);
                const float4 kb = *reinterpret_cast<const float4*>(g_qk + (size_t)sb * DM + 4 * t);
                const float4 vb = *reinterpret_cast<const float4*>(g_v  + (size_t)sb * DM + 4 * t);

                float pa = q.x * ka.x + q.y * ka.y + q.z * ka.z + q.w * ka.w;
                float pb = q.x * kb.x + q.y * kb.y + q.z * kb.z + q.w * kb.w;
                pa += __shfl_xor_sync(FULLM, pa, 1);
                pb += __shfl_xor_sync(FULLM, pb, 1);
                pa += __shfl_xor_sync(FULLM, pa, 2);
                pb += __shfl_xor_sync(FULLM, pb, 2);

                float exa = __expf(pa);
                float exb = __expf(pb);
                if ((t & 3) == 0) {
                    attn[(size_t)ea * 4 + hq] = exa;
                    attn[(size_t)eb * 4 + hq] = exb;
                }
                z += exa + exb;

                x0 += exa * va.x;  x1 += exa * va.y;  x2 += exa * va.z;  x3 += exa * va.w;
                x0 += exb * vb.x;  x1 += exb * vb.y;  x2 += exb * vb.z;  x3 += exb * vb.w;
            }
            // remainder: 2 edges per iteration, guarded
            for (; base < end; base += 2) {
                int e = base + eo;
                bool act = (e < end);
                int ec = act ? e : (end - 1);
                int s = senders[ec];
                float4 k4 = *reinterpret_cast<const float4*>(g_qk + (size_t)s * DM + 4 * t);
                float4 v4 = *reinterpret_cast<const float4*>(g_v  + (size_t)s * DM + 4 * t);
                float p = q.x * k4.x + q.y * k4.y + q.z * k4.z + q.w * k4.w;
                p += __shfl_xor_sync(FULLM, p, 1);
                p += __shfl_xor_sync(FULLM, p, 2);
                float ex = act ? __expf(p) : 0.f;
                if (act && (t & 3) == 0) attn[(size_t)e * 4 + hq] = ex;
                z += ex;
                x0 += ex * v4.x;  x1 += ex * v4.y;  x2 += ex * v4.z;  x3 += ex * v4.w;
            }

            z += __shfl_xor_sync(FULLM, z, 16);
            const float invz = 1.0f / z;

            x0 += __shfl_xor_sync(FULLM, x0, 16);
            x1 += __shfl_xor_sync(FULLM, x1, 16);
            x2 += __shfl_xor_sync(FULLM, x2, 16);
            x3 += __shfl_xor_sync(FULLM, x3, 16);
            x0 *= invz; x1 *= invz; x2 *= invz; x3 *= invz;

            // ---- normalize staged attn in place ----
            __syncwarp();                 // order staged stores before re-reads
            const float invz_h = __shfl_sync(FULLM, invz, h4 * 4);
            for (int b2 = beg; b2 < end; b2 += 8) {
                int e = b2 + eo8;
                if (e < end) attn[(size_t)e * 4 + h4] *= invz_h;
            }
        }

        // ---- fused out projection: out[n] = ctx @ W_out + b_out ----
        // after the xor-16 merge, every lane holds ctx dims 4t..4t+3
        if (lane < 16)
            *reinterpret_cast<float4*>(&ctx_s[warp][4 * t]) =
                make_float4(x0, x1, x2, x3);
        __syncwarp();

        float acc0 = bo_s[2 * lane];
        float acc1 = bo_s[2 * lane + 1];
#pragma unroll
        for (int k4 = 0; k4 < 16; k4++) {
            float4 cv = *reinterpret_cast<const float4*>(&ctx_s[warp][4 * k4]);
            float2 w0 = *reinterpret_cast<const float2*>(&wo_s[(4 * k4 + 0) * DM + 2 * lane]);
            float2 w1 = *reinterpret_cast<const float2*>(&wo_s[(4 * k4 + 1) * DM + 2 * lane]);
            float2 w2 = *reinterpret_cast<const float2*>(&wo_s[(4 * k4 + 2) * DM + 2 * lane]);
            float2 w3 = *reinterpret_cast<const float2*>(&wo_s[(4 * k4 + 3) * DM + 2 * lane]);
            acc0 += cv.x * w0.x + cv.y * w1.x + cv.z * w2.x + cv.w * w3.x;
            acc1 += cv.x * w0.y + cv.y * w1.y + cv.z * w2.y + cv.w * w3.y;
        }
        *reinterpret_cast<float2*>(out + (size_t)n * DM + 2 * lane) =
            make_float2(acc0, acc1);
        __syncwarp();                     // ctx_s reuse guard for next node
    }
}

// ---------------- launch ----------------
extern "C" void kernel_launch(void* const* d_in, const int* in_sizes, int n_in,
                              void* d_out, int out_size)
{
    const float* nodes   = (const float*)d_in[0];
    const float* W_qk    = (const float*)d_in[1];
    const float* b_qk    = (const float*)d_in[2];
    const float* W_v     = (const float*)d_in[3];
    const float* b_v     = (const float*)d_in[4];
    const float* W_out   = (const float*)d_in[5];
    const float* b_out   = (const float*)d_in[6];
    const int*   senders = (const int*)d_in[7];
    const int*   recv    = (const int*)d_in[8];

    float *qk_p = nullptr, *v_p = nullptr, *attn_fb = nullptr, *out_fb = nullptr;
    cudaGetSymbolAddress((void**)&qk_p,    g_qk);
    cudaGetSymbolAddress((void**)&v_p,     g_v);
    cudaGetSymbolAddress((void**)&attn_fb, g_attn_fb);
    cudaGetSymbolAddress((void**)&out_fb,  g_out_fb);

    const long long OUT_E  = (long long)N_NODES * DM;   // 6,400,000
    const long long ATTN_E = (long long)N_EDGES * 4;    // 4,000,000

    float* out_ptr;
    float* attn_ptr;
    if ((long long)out_size >= OUT_E + ATTN_E) {
        out_ptr  = (float*)d_out;
        attn_ptr = (float*)d_out + OUT_E;
    } else if ((long long)out_size == ATTN_E) {
        attn_ptr = (float*)d_out;
        out_ptr  = out_fb;
    } else {
        out_ptr  = (float*)d_out;
        attn_ptr = attn_fb;
    }

    // 8 warps/block, NPW nodes per warp
    const int edge_grid = (N_NODES + 8 * NPW - 1) / (8 * NPW);   // 1563

    offsets_kernel<<<(N_NODES + 1 + 255) / 256, 256>>>(recv);
    gemm_qkv_kernel<<<GEMM_BLOCKS, 256>>>(nodes, W_qk, b_qk, W_v, b_v, qk_p, v_p, N_NODES);
    fused_edge_kernel<<<edge_grid, 256>>>(senders, attn_ptr, W_out, b_out, out_ptr);
}

// round 17
// speedup vs baseline: 1.2998x; 1.2998x over previous
#include <cuda_runtime.h>
#include <math.h>

#define N_NODES 100000
#define N_EDGES 1000000
#define DM 64            // model dim (= H*D)
#define FULLM 0xffffffffu

#define BM 128
#define BN 64
#define BK 32
#define GEMM_BLOCKS ((N_NODES + BM - 1) / BM)          // 782
#define NPW 8            // nodes per warp in the edge kernel

// ---------------- scratch (device globals: allocation-free) ----------------
__device__ float g_qk[(size_t)N_NODES * DM];
__device__ float g_v[(size_t)N_NODES * DM];
__device__ float g_ctx[(size_t)N_NODES * DM];
__device__ int   g_off[N_NODES + 1];
__device__ float g_attn_fb[(size_t)N_EDGES * 4];
__device__ float g_out_fb[(size_t)N_NODES * DM];

// ---------------- f32x2 packed-FMA helpers (sm_100+) ----------------
__device__ __forceinline__ unsigned long long pack2(float lo, float hi) {
    unsigned long long r;
    asm("mov.b64 %0, {%1,%2};" : "=l"(r) : "f"(lo), "f"(hi));
    return r;
}
__device__ __forceinline__ void unpack2(unsigned long long p, float& lo, float& hi) {
    asm("mov.b64 {%0,%1}, %2;" : "=f"(lo), "=f"(hi) : "l"(p));
}
__device__ __forceinline__ void ffma2(unsigned long long& c, unsigned long long a, unsigned long long b) {
    asm("fma.rn.f32x2 %0, %1, %2, %0;" : "+l"(c) : "l"(a), "l"(b));
}

// ---------------- fused projection GEMM: qk = A@W_qk + b_qk ; v = A@W_v + b_v ----------------
// (champion version, byte-identical)
__global__ __launch_bounds__(256) void gemm_qkv_kernel(
    const float* __restrict__ A,
    const float* __restrict__ W1, const float* __restrict__ b1,
    const float* __restrict__ W2, const float* __restrict__ b2,
    float* __restrict__ C1, float* __restrict__ C2, int M)
{
    __shared__ float As[BK][BM + 4];
    __shared__ float W1s[BK][BN + 4];
    __shared__ float W2s[BK][BN + 4];

    const int tid = threadIdx.x;
    const int tx = tid & 15;
    const int ty = tid >> 4;
    const int bm = blockIdx.x * BM;

    unsigned long long acc1[4][4], acc2[4][4];
#pragma unroll
    for (int i = 0; i < 4; i++)
#pragma unroll
        for (int j = 0; j < 4; j++) { acc1[i][j] = pack2(0.f, 0.f); acc2[i][j] = pack2(0.f, 0.f); }

    for (int kk = 0; kk < DM; kk += BK) {
#pragma unroll
        for (int i = 0; i < 4; i++) {
            int idx = tid + i * 256;
            int r = idx >> 3;
            int c4 = idx & 7;
            float4 v = make_float4(0.f, 0.f, 0.f, 0.f);
            if (bm + r < M)
                v = reinterpret_cast<const float4*>(A + (size_t)(bm + r) * DM + kk)[c4];
            As[c4 * 4 + 0][r] = v.x;
            As[c4 * 4 + 1][r] = v.y;
            As[c4 * 4 + 2][r] = v.z;
            As[c4 * 4 + 3][r] = v.w;
        }
#pragma unroll
        for (int i = 0; i < 2; i++) {
            int idx = tid + i * 256;
            int kr = idx >> 4;
            int c4 = idx & 15;
            float4 v1 = reinterpret_cast<const float4*>(W1 + (size_t)(kk + kr) * DM)[c4];
            float4 v2 = reinterpret_cast<const float4*>(W2 + (size_t)(kk + kr) * DM)[c4];
            *reinterpret_cast<float4*>(&W1s[kr][c4 * 4]) = v1;
            *reinterpret_cast<float4*>(&W2s[kr][c4 * 4]) = v2;
        }
        __syncthreads();

#pragma unroll
        for (int k = 0; k < BK; k++) {
            unsigned long long ap[4];
#pragma unroll
            for (int i = 0; i < 4; i++) {
                float2 a = *reinterpret_cast<const float2*>(&As[k][ty * 8 + 2 * i]);
                ap[i] = pack2(a.x, a.y);
            }
            float4 w1 = *reinterpret_cast<const float4*>(&W1s[k][tx * 4]);
            unsigned long long wd1[4];
            wd1[0] = pack2(w1.x, w1.x); wd1[1] = pack2(w1.y, w1.y);
            wd1[2] = pack2(w1.z, w1.z); wd1[3] = pack2(w1.w, w1.w);
#pragma unroll
            for (int i = 0; i < 4; i++)
#pragma unroll
                for (int j = 0; j < 4; j++) ffma2(acc1[i][j], ap[i], wd1[j]);
            float4 w2 = *reinterpret_cast<const float4*>(&W2s[k][tx * 4]);
            unsigned long long wd2[4];
            wd2[0] = pack2(w2.x, w2.x); wd2[1] = pack2(w2.y, w2.y);
            wd2[2] = pack2(w2.z, w2.z); wd2[3] = pack2(w2.w, w2.w);
#pragma unroll
            for (int i = 0; i < 4; i++)
#pragma unroll
                for (int j = 0; j < 4; j++) ffma2(acc2[i][j], ap[i], wd2[j]);
        }
        __syncthreads();
    }

    float4 bv1 = *reinterpret_cast<const float4*>(b1 + tx * 4);
    float4 bv2 = *reinterpret_cast<const float4*>(b2 + tx * 4);
#pragma unroll
    for (int i = 0; i < 4; i++) {
        int r0 = bm + ty * 8 + 2 * i;
        float lo[4], hi[4];
#pragma unroll
        for (int j = 0; j < 4; j++) unpack2(acc1[i][j], lo[j], hi[j]);
        if (r0 < M)
            *reinterpret_cast<float4*>(C1 + (size_t)r0 * DM + tx * 4) =
                make_float4(lo[0] + bv1.x, lo[1] + bv1.y, lo[2] + bv1.z, lo[3] + bv1.w);
        if (r0 + 1 < M)
            *reinterpret_cast<float4*>(C1 + (size_t)(r0 + 1) * DM + tx * 4) =
                make_float4(hi[0] + bv1.x, hi[1] + bv1.y, hi[2] + bv1.z, hi[3] + bv1.w);
#pragma unroll
        for (int j = 0; j < 4; j++) unpack2(acc2[i][j], lo[j], hi[j]);
        if (r0 < M)
            *reinterpret_cast<float4*>(C2 + (size_t)r0 * DM + tx * 4) =
                make_float4(lo[0] + bv2.x, lo[1] + bv2.y, lo[2] + bv2.z, lo[3] + bv2.w);
        if (r0 + 1 < M)
            *reinterpret_cast<float4*>(C2 + (size_t)(r0 + 1) * DM + tx * 4) =
                make_float4(hi[0] + bv2.x, hi[1] + bv2.y, hi[2] + bv2.z, hi[3] + bv2.w);
    }
}

// ---------------- single GEMM (out projection; champion version) ----------------
__global__ __launch_bounds__(256) void gemm_n64_kernel(
    const float* __restrict__ A, const float* __restrict__ W,
    const float* __restrict__ bias, float* __restrict__ C, int M)
{
    __shared__ float As[BK][BM + 4];
    __shared__ float Ws[BK][BN + 4];

    const int tid = threadIdx.x;
    const int tx = tid & 15;
    const int ty = tid >> 4;
    const int bm = blockIdx.x * BM;

    unsigned long long acc2[4][4];
#pragma unroll
    for (int i = 0; i < 4; i++)
#pragma unroll
        for (int j = 0; j < 4; j++) acc2[i][j] = pack2(0.f, 0.f);

    for (int kk = 0; kk < DM; kk += BK) {
#pragma unroll
        for (int i = 0; i < 4; i++) {
            int idx = tid + i * 256;
            int r = idx >> 3;
            int c4 = idx & 7;
            float4 v = make_float4(0.f, 0.f, 0.f, 0.f);
            if (bm + r < M)
                v = reinterpret_cast<const float4*>(A + (size_t)(bm + r) * DM + kk)[c4];
            As[c4 * 4 + 0][r] = v.x;
            As[c4 * 4 + 1][r] = v.y;
            As[c4 * 4 + 2][r] = v.z;
            As[c4 * 4 + 3][r] = v.w;
        }
#pragma unroll
        for (int i = 0; i < 2; i++) {
            int idx = tid + i * 256;
            int kr = idx >> 4;
            int c4 = idx & 15;
            float4 v = reinterpret_cast<const float4*>(W + (size_t)(kk + kr) * DM)[c4];
            *reinterpret_cast<float4*>(&Ws[kr][c4 * 4]) = v;
        }
        __syncthreads();

#pragma unroll
        for (int k = 0; k < BK; k++) {
            float4 w = *reinterpret_cast<const float4*>(&Ws[k][tx * 4]);
            unsigned long long wd[4];
            wd[0] = pack2(w.x, w.x); wd[1] = pack2(w.y, w.y);
            wd[2] = pack2(w.z, w.z); wd[3] = pack2(w.w, w.w);
            unsigned long long ap[4];
#pragma unroll
            for (int i = 0; i < 4; i++) {
                float2 a = *reinterpret_cast<const float2*>(&As[k][ty * 8 + 2 * i]);
                ap[i] = pack2(a.x, a.y);
            }
#pragma unroll
            for (int i = 0; i < 4; i++)
#pragma unroll
                for (int j = 0; j < 4; j++) ffma2(acc2[i][j], ap[i], wd[j]);
        }
        __syncthreads();
    }

    float4 bv = *reinterpret_cast<const float4*>(bias + tx * 4);
#pragma unroll
    for (int i = 0; i < 4; i++) {
        float lo[4], hi[4];
#pragma unroll
        for (int j = 0; j < 4; j++) unpack2(acc2[i][j], lo[j], hi[j]);
        int r0 = bm + ty * 8 + 2 * i;
        if (r0 < M)
            *reinterpret_cast<float4*>(C + (size_t)r0 * DM + tx * 4) =
                make_float4(lo[0] + bv.x, lo[1] + bv.y, lo[2] + bv.z, lo[3] + bv.w);
        if (r0 + 1 < M)
            *reinterpret_cast<float4*>(C + (size_t)(r0 + 1) * DM + tx * 4) =
                make_float4(hi[0] + bv.x, hi[1] + bv.y, hi[2] + bv.z, hi[3] + bv.w);
    }
}

// ---------------- segment offsets: edge-parallel difference scatter ----------------
// Thread e: if recv[e] != recv[e-1], write g_off[n] = e for every node n in
// (recv[e-1], recv[e]]. Coalesced reads, sparse writes, no dependent chains.
// Boundaries: e==0 fills [0, recv[0]]; the last thread fills (recv[E-1], N].
__global__ void offsets_kernel(const int* __restrict__ recv) {
    int e = blockIdx.x * blockDim.x + threadIdx.x;
    if (e >= N_EDGES) return;
    int r  = recv[e];
    int rp = (e == 0) ? -1 : recv[e - 1];
    for (int n = rp + 1; n <= r; n++) g_off[n] = e;
    if (e == N_EDGES - 1)
        for (int n = r + 1; n <= N_NODES; n++) g_off[n] = N_EDGES;
}

// ---------------- fully fused edge kernel (champion, byte-identical) ----------------
// Per-node body: 4-edge main loop, scalar FFMA; NPW=8 contiguous nodes/warp.
__global__ __launch_bounds__(256) void fused_edge_kernel(
    const int* __restrict__ senders, float* attn)
{
    const int warp = threadIdx.x >> 5;
    const int lane = threadIdx.x & 31;
    const int gwarp = blockIdx.x * 8 + warp;

    const int t  = lane & 15;
    const int eo = lane >> 4;
    const int hq = t >> 2;
    const int h4 = lane & 3;
    const int eo8 = lane >> 2;

    for (int ni = 0; ni < NPW; ni++) {
        const int n = gwarp * NPW + ni;
        if (n >= N_NODES) return;

        const int beg = g_off[n];
        const int end = g_off[n + 1];

        float x0 = 0.f, x1 = 0.f, x2 = 0.f, x3 = 0.f;

        if (beg < end) {
            const float4 q = *reinterpret_cast<const float4*>(g_qk + (size_t)n * DM + 4 * t);
            float z = 0.f;

            int base = beg;
            // main loop: 4 edges per iteration, no guards
            for (; base + 3 < end; base += 4) {
                int ea = base + eo;
                int eb = base + 2 + eo;
                int sa = senders[ea];
                int sb = senders[eb];
                const float4 ka = *reinterpret_cast<const float4*>(g_qk + (size_t)sa * DM + 4 * t);
                const float4 va = *reinterpret_cast<const float4*>(g_v  + (size_t)sa * DM + 4 * t);
                const float4 kb = *reinterpret_cast<const float4*>(g_qk + (size_t)sb * DM + 4 * t);
                const float4 vb = *reinterpret_cast<const float4*>(g_v  + (size_t)sb * DM + 4 * t);

                float pa = q.x * ka.x + q.y * ka.y + q.z * ka.z + q.w * ka.w;
                float pb = q.x * kb.x + q.y * kb.y + q.z * kb.z + q.w * kb.w;
                pa += __shfl_xor_sync(FULLM, pa, 1);
                pb += __shfl_xor_sync(FULLM, pb, 1);
                pa += __shfl_xor_sync(FULLM, pa, 2);
                pb += __shfl_xor_sync(FULLM, pb, 2);

                float exa = __expf(pa);
                float exb = __expf(pb);
                if ((t & 3) == 0) {
                    attn[(size_t)ea * 4 + hq] = exa;
                    attn[(size_t)eb * 4 + hq] = exb;
                }
                z += exa + exb;

                x0 += exa * va.x;  x1 += exa * va.y;  x2 += exa * va.z;  x3 += exa * va.w;
                x0 += exb * vb.x;  x1 += exb * vb.y;  x2 += exb * vb.z;  x3 += exb * vb.w;
            }
            // remainder: 2 edges per iteration, guarded
            for (; base < end; base += 2) {
                int e = base + eo;
                bool act = (e < end);
                int ec = act ? e : (end - 1);
                int s = senders[ec];
                float4 k4 = *reinterpret_cast<const float4*>(g_qk + (size_t)s * DM + 4 * t);
                float4 v4 = *reinterpret_cast<const float4*>(g_v  + (size_t)s * DM + 4 * t);
                float p = q.x * k4.x + q.y * k4.y + q.z * k4.z + q.w * k4.w;
                p += __shfl_xor_sync(FULLM, p, 1);
                p += __shfl_xor_sync(FULLM, p, 2);
                float ex = act ? __expf(p) : 0.f;
                if (act && (t & 3) == 0) attn[(size_t)e * 4 + hq] = ex;
                z += ex;
                x0 += ex * v4.x;  x1 += ex * v4.y;  x2 += ex * v4.z;  x3 += ex * v4.w;
            }

            z += __shfl_xor_sync(FULLM, z, 16);
            const float invz = 1.0f / z;

            x0 += __shfl_xor_sync(FULLM, x0, 16);
            x1 += __shfl_xor_sync(FULLM, x1, 16);
            x2 += __shfl_xor_sync(FULLM, x2, 16);
            x3 += __shfl_xor_sync(FULLM, x3, 16);
            x0 *= invz; x1 *= invz; x2 *= invz; x3 *= invz;

            // ---- normalize staged attn in place ----
            __syncwarp();                 // order staged stores before re-reads
            const float invz_h = __shfl_sync(FULLM, invz, h4 * 4);
            for (int b2 = beg; b2 < end; b2 += 8) {
                int e = b2 + eo8;
                if (e < end) attn[(size_t)e * 4 + h4] *= invz_h;
            }
        }

        if (lane < 16)
            *reinterpret_cast<float4*>(g_ctx + (size_t)n * DM + 4 * t) =
                make_float4(x0, x1, x2, x3);
    }
}

// ---------------- launch ----------------
extern "C" void kernel_launch(void* const* d_in, const int* in_sizes, int n_in,
                              void* d_out, int out_size)
{
    const float* nodes   = (const float*)d_in[0];
    const float* W_qk    = (const float*)d_in[1];
    const float* b_qk    = (const float*)d_in[2];
    const float* W_v     = (const float*)d_in[3];
    const float* b_v     = (const float*)d_in[4];
    const float* W_out   = (const float*)d_in[5];
    const float* b_out   = (const float*)d_in[6];
    const int*   senders = (const int*)d_in[7];
    const int*   recv    = (const int*)d_in[8];

    float *qk_p = nullptr, *v_p = nullptr, *ctx_p = nullptr, *attn_fb = nullptr, *out_fb = nullptr;
    cudaGetSymbolAddress((void**)&qk_p,    g_qk);
    cudaGetSymbolAddress((void**)&v_p,     g_v);
    cudaGetSymbolAddress((void**)&ctx_p,   g_ctx);
    cudaGetSymbolAddress((void**)&attn_fb, g_attn_fb);
    cudaGetSymbolAddress((void**)&out_fb,  g_out_fb);

    const long long OUT_E  = (long long)N_NODES * DM;   // 6,400,000
    const long long ATTN_E = (long long)N_EDGES * 4;    // 4,000,000

    float* out_ptr;
    float* attn_ptr;
    if ((long long)out_size >= OUT_E + ATTN_E) {
        out_ptr  = (float*)d_out;
        attn_ptr = (float*)d_out + OUT_E;
    } else if ((long long)out_size == ATTN_E) {
        attn_ptr = (float*)d_out;
        out_ptr  = out_fb;
    } else {
        out_ptr  = (float*)d_out;
        attn_ptr = attn_fb;
    }

    // 8 warps/block, NPW nodes per warp
    const int edge_grid = (N_NODES + 8 * NPW - 1) / (8 * NPW);   // 1563

    offsets_kernel<<<(N_EDGES + 255) / 256, 256>>>(recv);
    gemm_qkv_kernel<<<GEMM_BLOCKS, 256>>>(nodes, W_qk, b_qk, W_v, b_v, qk_p, v_p, N_NODES);
    fused_edge_kernel<<<edge_grid, 256>>>(senders, attn_ptr);
    gemm_n64_kernel<<<GEMM_BLOCKS, 256>>>(ctx_p, W_out, b_out, out_ptr, N_NODES);
}